// round 7
// baseline (speedup 1.0000x reference)
#include <cuda_runtime.h>

// ---------------- Problem constants ----------------
#define Bc  2
#define Sc  2048
#define Dc  1024
#define Hc  16
#define HDc 64
#define MROWS (Bc*Sc)                       // 4096
#define OUT_ELEMS  ((size_t)Bc*Sc*Dc)       // 4,194,304
#define ATTN_ELEMS ((size_t)Bc*Hc*Sc*Sc)    // 134,217,728

// ---------------- Scratch (static device globals; no allocation) ----------------
__device__ float g_q [Bc*Sc*Dc];
__device__ float g_k [Bc*Sc*Dc];
__device__ float g_v [Bc*Sc*Dc];
__device__ float g_av[Bc*Sc*Dc];
__device__ float g_out[Bc*Sc*Dc];
__device__ float g_attn[(size_t)Bc*Hc*Sc*Sc];   // fallback if attn not in d_out

__device__ __forceinline__ float load_clip(const int* p) {
    int iv = *p;
    if (iv >= -1000000 && iv <= 1000000) return (float)iv;  // stored as int
    return __int_as_float(iv);                              // stored as float bits
}

// ---------------- SGEMM: C[M,N] = A[M,K] @ W[K,N] + bias (+ optional relpos) ----------------
// M=4096, N=K=1024. BM=BN=128, BK=8, TM=TN=8, 256 threads.
__global__ __launch_bounds__(256) void sgemm_bias(
    const float* __restrict__ A, const float* __restrict__ Bw,
    const float* __restrict__ bias, float* __restrict__ Cout,
    int srcSel, int dstSel, int relMode, const int* __restrict__ clipPtr)
{
    const int Kd = Dc, Nd = Dc;
    __shared__ float As[8*128];
    __shared__ float Bs[8*128];

    const float* Ain = srcSel ? g_av : A;
    float* C;
    if (dstSel == 0)      C = g_q;
    else if (dstSel == 1) C = g_k;
    else if (dstSel == 2) C = g_v;
    else                  C = Cout ? Cout : g_out;

    const int bx = blockIdx.x, by = blockIdx.y;
    const int tid  = threadIdx.x;
    const int tRow = tid >> 4, tCol = tid & 15;
    const int aRow = tid >> 1, aCol = (tid & 1) << 2;
    const int bRow = tid >> 5, bCol = (tid & 31) << 2;

    const float* Ab = Ain + (size_t)by*128*Kd;
    const float* Bb = Bw + bx*128;

    float acc[8][8];
    #pragma unroll
    for (int i=0;i<8;i++)
        #pragma unroll
        for (int j=0;j<8;j++) acc[i][j]=0.f;

    for (int k0=0; k0<Kd; k0+=8) {
        float4 a4 = *(const float4*)(Ab + (size_t)aRow*Kd + k0 + aCol);
        As[(aCol+0)*128 + aRow] = a4.x;
        As[(aCol+1)*128 + aRow] = a4.y;
        As[(aCol+2)*128 + aRow] = a4.z;
        As[(aCol+3)*128 + aRow] = a4.w;
        *(float4*)(Bs + bRow*128 + bCol) =
            *(const float4*)(Bb + (size_t)(k0+bRow)*Nd + bCol);
        __syncthreads();
        #pragma unroll
        for (int kk=0; kk<8; kk++) {
            float4 a0 = *(const float4*)(As + kk*128 + tRow*8);
            float4 a1 = *(const float4*)(As + kk*128 + tRow*8 + 4);
            float4 b0 = *(const float4*)(Bs + kk*128 + tCol*8);
            float4 b1 = *(const float4*)(Bs + kk*128 + tCol*8 + 4);
            float ar[8] = {a0.x,a0.y,a0.z,a0.w,a1.x,a1.y,a1.z,a1.w};
            float br[8] = {b0.x,b0.y,b0.z,b0.w,b1.x,b1.y,b1.z,b1.w};
            #pragma unroll
            for (int i=0;i<8;i++)
                #pragma unroll
                for (int j=0;j<8;j++)
                    acc[i][j] = fmaf(ar[i], br[j], acc[i][j]);
        }
        __syncthreads();
    }

    const float clipv = relMode ? load_clip(clipPtr) : 0.f;
    #pragma unroll
    for (int i=0;i<8;i++) {
        const int r = by*128 + tRow*8 + i;
        const int s = r & (Sc-1);          // row within sequence
        #pragma unroll
        for (int j0=0;j0<8;j0+=4) {
            float4 v;
            float* vp = &v.x;
            #pragma unroll
            for (int j=0;j<4;j++) {
                const int c = bx*128 + tCol*8 + j0 + j;
                float x = acc[i][j0+j] + bias[c];
                if (relMode) {
                    float rp = (float)(c - s);
                    rp = fminf(fmaxf(rp, -clipv), clipv);
                    x += rp;
                }
                vp[j] = x;
            }
            *(float4*)(C + (size_t)r*Nd + bx*128 + tCol*8 + j0) = v;
        }
    }
}

// ---------------- Fused attention per (b, h, 128-row q tile) ----------------
// Phase 1: scores = (Q Kᵀ)/32 * mask  -> raw scores to attn buf, online row max/sum
// Phase 2: probs = softmax(scores)    -> attn buf, + AV accumulate -> g_av
// smem: Qs/Ps 128x65, KVs 64x65, rowM/rowL 128 each = 50,944 B (dynamic)
__global__ __launch_bounds__(256) void attn_kernel(const float* __restrict__ mask,
                                                   float* __restrict__ attn_io)
{
    extern __shared__ float sm[];
    float* Qs   = sm;                 // 128*65
    float* KVs  = sm + 128*65;        // 64*65
    float* rowM = KVs + 64*65;        // 128
    float* rowL = rowM + 128;         // 128
    float* Ps   = Qs;                 // phase-2 overlay

    float* attn = attn_io ? attn_io : g_attn;

    const int b  = blockIdx.z, h = blockIdx.y;
    const int q0 = blockIdx.x * 128;
    const int tid = threadIdx.x;
    const int tq = tid >> 4, tk = tid & 15;

    const size_t headoff = (size_t)b*Sc*Dc + (size_t)h*Sc*HDc;
    const float* Qb = g_q + headoff;
    const float* Kb = g_k + headoff;
    const float* Vb = g_v + headoff;
    const float* Mb = mask + (size_t)b*Sc*Sc;
    float* Ab = attn + (size_t)(b*Hc + h)*Sc*Sc;

    // Load Q tile [128][64] into padded smem
    for (int f = tid; f < 128*16; f += 256) {
        int r = f >> 4, c4 = (f & 15) << 2;
        float4 v = *(const float4*)(Qb + (size_t)(q0 + r)*HDc + c4);
        float* dst = Qs + r*65 + c4;
        dst[0]=v.x; dst[1]=v.y; dst[2]=v.z; dst[3]=v.w;
    }

    float m_i[8], l_i[8];
    #pragma unroll
    for (int i=0;i<8;i++){ m_i[i] = -3.0e38f; l_i[i] = 0.f; }
    const float scale = 0.03125f;   // 1/sqrt(D), D=1024

    // ---- Phase 1 ----
    for (int kt=0; kt<Sc; kt+=64) {
        __syncthreads();
        for (int f = tid; f < 64*16; f += 256) {
            int r = f >> 4, c4 = (f & 15) << 2;
            float4 v = *(const float4*)(Kb + (size_t)(kt + r)*HDc + c4);
            float* dst = KVs + r*65 + c4;
            dst[0]=v.x; dst[1]=v.y; dst[2]=v.z; dst[3]=v.w;
        }
        __syncthreads();

        float acc[8][4];
        #pragma unroll
        for (int i=0;i<8;i++)
            #pragma unroll
            for (int j=0;j<4;j++) acc[i][j]=0.f;

        #pragma unroll 4
        for (int d=0; d<64; d++) {
            float qv[8], kv[4];
            #pragma unroll
            for (int i=0;i<8;i++) qv[i] = Qs[(tq*8+i)*65 + d];
            #pragma unroll
            for (int j=0;j<4;j++) kv[j] = KVs[(tk*4+j)*65 + d];
            #pragma unroll
            for (int i=0;i<8;i++)
                #pragma unroll
                for (int j=0;j<4;j++)
                    acc[i][j] = fmaf(qv[i], kv[j], acc[i][j]);
        }

        #pragma unroll
        for (int i=0;i<8;i++) {
            const int qg = q0 + tq*8 + i;
            const size_t rowoff = (size_t)qg*Sc + kt + tk*4;
            float s[4];
            float mx = m_i[i];
            #pragma unroll
            for (int j=0;j<4;j++) {
                s[j] = acc[i][j]*scale * Mb[rowoff + j];
                Ab[rowoff + j] = s[j];            // raw masked score
                mx = fmaxf(mx, s[j]);
            }
            float l = l_i[i]*__expf(m_i[i]-mx);
            #pragma unroll
            for (int j=0;j<4;j++) l += __expf(s[j]-mx);
            m_i[i]=mx; l_i[i]=l;
        }
    }

    // Cross-lane reduce over the 16 lanes of each q row (half-warp segments)
    #pragma unroll
    for (int i=0;i<8;i++) {
        float m = m_i[i], l = l_i[i];
        #pragma unroll
        for (int off=8; off; off>>=1) {
            float mo = __shfl_xor_sync(0xffffffffu, m, off, 16);
            float lo = __shfl_xor_sync(0xffffffffu, l, off, 16);
            float mn = fmaxf(m, mo);
            l = l*__expf(m-mn) + lo*__expf(mo-mn);
            m = mn;
        }
        if (tk==0) { rowM[tq*8+i] = m; rowL[tq*8+i] = 1.0f/l; }
    }

    // ---- Phase 2 ----
    float av[8][4];
    #pragma unroll
    for (int i=0;i<8;i++)
        #pragma unroll
        for (int j=0;j<4;j++) av[i][j]=0.f;

    for (int kt=0; kt<Sc; kt+=64) {
        __syncthreads();
        for (int f = tid; f < 64*16; f += 256) {
            int r = f >> 4, c4 = (f & 15) << 2;
            float4 v = *(const float4*)(Vb + (size_t)(kt + r)*HDc + c4);
            float* dst = KVs + r*65 + c4;
            dst[0]=v.x; dst[1]=v.y; dst[2]=v.z; dst[3]=v.w;
        }
        #pragma unroll
        for (int i=0;i<8;i++) {
            const int qloc = tq*8+i;
            const int qg = q0 + qloc;
            const size_t rowoff = (size_t)qg*Sc + kt + tk*4;
            const float M = rowM[qloc], iL = rowL[qloc];
            #pragma unroll
            for (int j=0;j<4;j++) {
                float p = __expf(Ab[rowoff+j] - M) * iL;   // same thread wrote it: ordered
                Ab[rowoff+j] = p;                           // final attn probability
                Ps[qloc*65 + tk*4 + j] = p;
            }
        }
        __syncthreads();
        #pragma unroll 4
        for (int k=0;k<64;k++) {
            float pv[8], vv[4];
            #pragma unroll
            for (int i=0;i<8;i++) pv[i] = Ps[(tq*8+i)*65 + k];
            #pragma unroll
            for (int j=0;j<4;j++) vv[j] = KVs[k*65 + tk*4 + j];
            #pragma unroll
            for (int i=0;i<8;i++)
                #pragma unroll
                for (int j=0;j<4;j++)
                    av[i][j] = fmaf(pv[i], vv[j], av[i][j]);
        }
    }

    float* AVb = g_av + headoff;
    #pragma unroll
    for (int i=0;i<8;i++) {
        const int q = q0 + tq*8 + i;
        float4 v4 = make_float4(av[i][0],av[i][1],av[i][2],av[i][3]);
        *(float4*)(AVb + (size_t)q*HDc + tk*4) = v4;
    }
}

// ---------------- Launch ----------------
extern "C" void kernel_launch(void* const* d_in, const int* in_sizes, int n_in,
                              void* d_out, int out_size)
{
    const float* inputs  = (const float*)d_in[0];
    const float* context = (const float*)d_in[1];
    const float* mask    = (const float*)d_in[2];
    const float* Wq = (const float*)d_in[3];
    const float* bq = (const float*)d_in[4];
    const float* Wk = (const float*)d_in[5];
    const float* bk = (const float*)d_in[6];
    const float* Wv = (const float*)d_in[7];
    const float* bv = (const float*)d_in[8];
    const float* Wo = (const float*)d_in[9];
    const float* bo = (const float*)d_in[10];
    const int* clip = (const int*)d_in[11];

    // Decide output layout from out_size: out-only / out+attn / attn-only
    float* outPtr  = (float*)d_out;       // nullptr -> kernel writes g_out scratch
    float* attnPtr = nullptr;             // nullptr -> kernel writes g_attn scratch
    const size_t osz = (size_t)out_size;
    if (osz >= OUT_ELEMS + ATTN_ELEMS) {
        attnPtr = (float*)d_out + OUT_ELEMS;
    } else if (osz == ATTN_ELEMS) {
        attnPtr = (float*)d_out;
        outPtr  = nullptr;
    }

    dim3 gproj(Dc/128, MROWS/128);   // (8, 32)

    // q = inputs@Wq + bq + relpos ; k = context@Wk + bk ; v = context@Wv + bv + relpos
    sgemm_bias<<<gproj, 256>>>(inputs,  Wq, bq, nullptr, 0, 0, 1, clip);
    sgemm_bias<<<gproj, 256>>>(context, Wk, bk, nullptr, 0, 1, 0, clip);
    sgemm_bias<<<gproj, 256>>>(context, Wv, bv, nullptr, 0, 2, 1, clip);

    const int attnSmem = (128*65 + 64*65 + 256) * 4;   // 50,944 B
    cudaFuncSetAttribute(attn_kernel, cudaFuncAttributeMaxDynamicSharedMemorySize, attnSmem);
    attn_kernel<<<dim3(Sc/128, Hc, Bc), 256, attnSmem>>>(mask, attnPtr);

    // out = av @ Wo + bo
    sgemm_bias<<<gproj, 256>>>(nullptr, Wo, bo, outPtr, 1, 3, 0, clip);
}

// round 11
// speedup vs baseline: 1.0522x; 1.0522x over previous
#include <cuda_runtime.h>

// ---------------- Problem constants ----------------
#define Bc  2
#define Sc  2048
#define Dc  1024
#define Hc  16
#define HDc 64
#define MROWS (Bc*Sc)                       // 4096
#define OUT_ELEMS  ((size_t)Bc*Sc*Dc)       // 4,194,304
#define ATTN_ELEMS ((size_t)Bc*Hc*Sc*Sc)    // 134,217,728
#define RPAD 68                             // smem row stride (floats), 16B-aligned

// ---------------- Scratch (static device globals; no allocation) ----------------
__device__ float g_q [Bc*Sc*Dc];
__device__ float g_k [Bc*Sc*Dc];
__device__ float g_v [Bc*Sc*Dc];
__device__ float g_av[Bc*Sc*Dc];
__device__ float g_out[Bc*Sc*Dc];
__device__ float g_attn[(size_t)Bc*Hc*Sc*Sc];   // fallback if attn not in d_out

__device__ __forceinline__ float load_clip(const int* p) {
    int iv = *p;
    if (iv >= -1000000 && iv <= 1000000) return (float)iv;  // stored as int
    return __int_as_float(iv);                              // stored as float bits
}

// ---------------- SGEMM: C[M,N] = A[M,K] @ W[K,N] + bias (+ optional relpos) ----------------
// M=4096, N=K=1024. BM=BN=128, BK=8, TM=TN=8, 256 threads.  (unchanged from R7 baseline)
__global__ __launch_bounds__(256) void sgemm_bias(
    const float* __restrict__ A, const float* __restrict__ Bw,
    const float* __restrict__ bias, float* __restrict__ Cout,
    int srcSel, int dstSel, int relMode, const int* __restrict__ clipPtr)
{
    const int Kd = Dc, Nd = Dc;
    __shared__ float As[8*128];
    __shared__ float Bs[8*128];

    const float* Ain = srcSel ? g_av : A;
    float* C;
    if (dstSel == 0)      C = g_q;
    else if (dstSel == 1) C = g_k;
    else if (dstSel == 2) C = g_v;
    else                  C = Cout ? Cout : g_out;

    const int bx = blockIdx.x, by = blockIdx.y;
    const int tid  = threadIdx.x;
    const int tRow = tid >> 4, tCol = tid & 15;
    const int aRow = tid >> 1, aCol = (tid & 1) << 2;
    const int bRow = tid >> 5, bCol = (tid & 31) << 2;

    const float* Ab = Ain + (size_t)by*128*Kd;
    const float* Bb = Bw + bx*128;

    float acc[8][8];
    #pragma unroll
    for (int i=0;i<8;i++)
        #pragma unroll
        for (int j=0;j<8;j++) acc[i][j]=0.f;

    for (int k0=0; k0<Kd; k0+=8) {
        float4 a4 = *(const float4*)(Ab + (size_t)aRow*Kd + k0 + aCol);
        As[(aCol+0)*128 + aRow] = a4.x;
        As[(aCol+1)*128 + aRow] = a4.y;
        As[(aCol+2)*128 + aRow] = a4.z;
        As[(aCol+3)*128 + aRow] = a4.w;
        *(float4*)(Bs + bRow*128 + bCol) =
            *(const float4*)(Bb + (size_t)(k0+bRow)*Nd + bCol);
        __syncthreads();
        #pragma unroll
        for (int kk=0; kk<8; kk++) {
            float4 a0 = *(const float4*)(As + kk*128 + tRow*8);
            float4 a1 = *(const float4*)(As + kk*128 + tRow*8 + 4);
            float4 b0 = *(const float4*)(Bs + kk*128 + tCol*8);
            float4 b1 = *(const float4*)(Bs + kk*128 + tCol*8 + 4);
            float ar[8] = {a0.x,a0.y,a0.z,a0.w,a1.x,a1.y,a1.z,a1.w};
            float br[8] = {b0.x,b0.y,b0.z,b0.w,b1.x,b1.y,b1.z,b1.w};
            #pragma unroll
            for (int i=0;i<8;i++)
                #pragma unroll
                for (int j=0;j<8;j++)
                    acc[i][j] = fmaf(ar[i], br[j], acc[i][j]);
        }
        __syncthreads();
    }

    const float clipv = relMode ? load_clip(clipPtr) : 0.f;
    #pragma unroll
    for (int i=0;i<8;i++) {
        const int r = by*128 + tRow*8 + i;
        const int s = r & (Sc-1);          // row within sequence
        #pragma unroll
        for (int j0=0;j0<8;j0+=4) {
            float4 v;
            float* vp = &v.x;
            #pragma unroll
            for (int j=0;j<4;j++) {
                const int c = bx*128 + tCol*8 + j0 + j;
                float x = acc[i][j0+j] + bias[c];
                if (relMode) {
                    float rp = (float)(c - s);
                    rp = fminf(fmaxf(rp, -clipv), clipv);
                    x += rp;
                }
                vp[j] = x;
            }
            *(float4*)(C + (size_t)r*Nd + bx*128 + tCol*8 + j0) = v;
        }
    }
}

// ---------------- Fused attention per (b, h, 128-row q tile) ----------------
// R8: all smem inner-loop traffic is float4 (LDS.128). Row stride RPAD=68 floats:
//   - Q/P loads: broadcast across the 16 tk lanes.
//   - K loads (row = tk + 16*j): lane byte-stride 272 -> start-bank stride 4 -> 2-way max.
//   - V loads (float4 along row at tk*4): conflict-free.
// Thread tile unchanged: 8 q-rows x 4 k-cols; k-col mapping now tk + 16*j.
__global__ __launch_bounds__(256, 2) void attn_kernel(const float* __restrict__ mask,
                                                      float* __restrict__ attn_io)
{
    extern __shared__ float sm[];
    float* Qs   = sm;                     // 128*RPAD
    float* KVs  = sm + 128*RPAD;          // 64*RPAD
    float* rowM = KVs + 64*RPAD;          // 128
    float* rowL = rowM + 128;             // 128
    float* Ps   = Qs;                     // phase-2 overlay

    float* attn = attn_io ? attn_io : g_attn;

    const int b  = blockIdx.z, h = blockIdx.y;
    const int q0 = blockIdx.x * 128;
    const int tid = threadIdx.x;
    const int tq = tid >> 4, tk = tid & 15;

    const size_t headoff = (size_t)b*Sc*Dc + (size_t)h*Sc*HDc;
    const float* Qb = g_q + headoff;
    const float* Kb = g_k + headoff;
    const float* Vb = g_v + headoff;
    const float* Mb = mask + (size_t)b*Sc*Sc;
    float* Ab = attn + (size_t)(b*Hc + h)*Sc*Sc;

    // Load Q tile [128][64] into padded smem (float4 stores)
    for (int f = tid; f < 128*16; f += 256) {
        int r = f >> 4, c4 = (f & 15) << 2;
        float4 v = *(const float4*)(Qb + (size_t)(q0 + r)*HDc + c4);
        *(float4*)(Qs + r*RPAD + c4) = v;
    }

    float m_i[8], l_i[8];
    #pragma unroll
    for (int i=0;i<8;i++){ m_i[i] = -3.0e38f; l_i[i] = 0.f; }
    const float scale = 0.03125f;   // 1/sqrt(D), D=1024

    // ---- Phase 1: scores + online row max/sum ----
    for (int kt=0; kt<Sc; kt+=64) {
        __syncthreads();
        for (int f = tid; f < 64*16; f += 256) {
            int r = f >> 4, c4 = (f & 15) << 2;
            float4 v = *(const float4*)(Kb + (size_t)(kt + r)*HDc + c4);
            *(float4*)(KVs + r*RPAD + c4) = v;
        }
        __syncthreads();

        float acc[8][4];
        #pragma unroll
        for (int i=0;i<8;i++)
            #pragma unroll
            for (int j=0;j<4;j++) acc[i][j]=0.f;

        #pragma unroll 2
        for (int d4=0; d4<64; d4+=4) {
            float4 qv[8];
            #pragma unroll
            for (int i=0;i<8;i++) qv[i] = *(const float4*)(Qs + (tq*8+i)*RPAD + d4);
            float4 kv[4];
            #pragma unroll
            for (int j=0;j<4;j++) kv[j] = *(const float4*)(KVs + (tk + 16*j)*RPAD + d4);
            #pragma unroll
            for (int i=0;i<8;i++)
                #pragma unroll
                for (int j=0;j<4;j++) {
                    acc[i][j] = fmaf(qv[i].x, kv[j].x, acc[i][j]);
                    acc[i][j] = fmaf(qv[i].y, kv[j].y, acc[i][j]);
                    acc[i][j] = fmaf(qv[i].z, kv[j].z, acc[i][j]);
                    acc[i][j] = fmaf(qv[i].w, kv[j].w, acc[i][j]);
                }
        }

        #pragma unroll
        for (int i=0;i<8;i++) {
            const int qg = q0 + tq*8 + i;
            const size_t rowbase = (size_t)qg*Sc + kt;
            float s[4];
            float mx = m_i[i];
            #pragma unroll
            for (int j=0;j<4;j++) {
                const int col = tk + 16*j;
                s[j] = acc[i][j]*scale * Mb[rowbase + col];
                Ab[rowbase + col] = s[j];          // raw masked score
                mx = fmaxf(mx, s[j]);
            }
            float l = l_i[i]*__expf(m_i[i]-mx);
            #pragma unroll
            for (int j=0;j<4;j++) l += __expf(s[j]-mx);
            m_i[i]=mx; l_i[i]=l;
        }
    }

    // Cross-lane reduce over the 16 lanes of each q row (half-warp segments)
    #pragma unroll
    for (int i=0;i<8;i++) {
        float m = m_i[i], l = l_i[i];
        #pragma unroll
        for (int off=8; off; off>>=1) {
            float mo = __shfl_xor_sync(0xffffffffu, m, off, 16);
            float lo = __shfl_xor_sync(0xffffffffu, l, off, 16);
            float mn = fmaxf(m, mo);
            l = l*__expf(m-mn) + lo*__expf(mo-mn);
            m = mn;
        }
        if (tk==0) { rowM[tq*8+i] = m; rowL[tq*8+i] = 1.0f/l; }
    }

    // ---- Phase 2: probs + AV ----
    float av[8][4];
    #pragma unroll
    for (int i=0;i<8;i++)
        #pragma unroll
        for (int j=0;j<4;j++) av[i][j]=0.f;

    for (int kt=0; kt<Sc; kt+=64) {
        __syncthreads();                       // protect KVs/Ps from previous iter readers
        for (int f = tid; f < 64*16; f += 256) {
            int r = f >> 4, c4 = (f & 15) << 2;
            float4 v = *(const float4*)(Vb + (size_t)(kt + r)*HDc + c4);
            *(float4*)(KVs + r*RPAD + c4) = v;
        }
        #pragma unroll
        for (int i=0;i<8;i++) {
            const int qloc = tq*8+i;
            const int qg = q0 + qloc;
            const size_t rowbase = (size_t)qg*Sc + kt;
            const float M = rowM[qloc], iL = rowL[qloc];
            #pragma unroll
            for (int j=0;j<4;j++) {
                const int col = tk + 16*j;
                float p = __expf(Ab[rowbase+col] - M) * iL;  // same thread wrote it
                Ab[rowbase+col] = p;                          // final attn probability
                Ps[qloc*RPAD + col] = p;
            }
        }
        __syncthreads();
        #pragma unroll 2
        for (int k4=0; k4<64; k4+=4) {
            float4 pv[8];
            #pragma unroll
            for (int i=0;i<8;i++) pv[i] = *(const float4*)(Ps + (tq*8+i)*RPAD + k4);
            float4 vv[4];
            #pragma unroll
            for (int kk=0;kk<4;kk++) vv[kk] = *(const float4*)(KVs + (k4+kk)*RPAD + tk*4);
            #pragma unroll
            for (int i=0;i<8;i++) {
                av[i][0] = fmaf(pv[i].x, vv[0].x, av[i][0]);
                av[i][0] = fmaf(pv[i].y, vv[1].x, av[i][0]);
                av[i][0] = fmaf(pv[i].z, vv[2].x, av[i][0]);
                av[i][0] = fmaf(pv[i].w, vv[3].x, av[i][0]);
                av[i][1] = fmaf(pv[i].x, vv[0].y, av[i][1]);
                av[i][1] = fmaf(pv[i].y, vv[1].y, av[i][1]);
                av[i][1] = fmaf(pv[i].z, vv[2].y, av[i][1]);
                av[i][1] = fmaf(pv[i].w, vv[3].y, av[i][1]);
                av[i][2] = fmaf(pv[i].x, vv[0].z, av[i][2]);
                av[i][2] = fmaf(pv[i].y, vv[1].z, av[i][2]);
                av[i][2] = fmaf(pv[i].z, vv[2].z, av[i][2]);
                av[i][2] = fmaf(pv[i].w, vv[3].z, av[i][2]);
                av[i][3] = fmaf(pv[i].x, vv[0].w, av[i][3]);
                av[i][3] = fmaf(pv[i].y, vv[1].w, av[i][3]);
                av[i][3] = fmaf(pv[i].z, vv[2].w, av[i][3]);
                av[i][3] = fmaf(pv[i].w, vv[3].w, av[i][3]);
            }
        }
    }

    float* AVb = g_av + headoff;
    #pragma unroll
    for (int i=0;i<8;i++) {
        const int q = q0 + tq*8 + i;
        float4 v4 = make_float4(av[i][0],av[i][1],av[i][2],av[i][3]);
        *(float4*)(AVb + (size_t)q*HDc + tk*4) = v4;
    }
}

// ---------------- Launch ----------------
extern "C" void kernel_launch(void* const* d_in, const int* in_sizes, int n_in,
                              void* d_out, int out_size)
{
    const float* inputs  = (const float*)d_in[0];
    const float* context = (const float*)d_in[1];
    const float* mask    = (const float*)d_in[2];
    const float* Wq = (const float*)d_in[3];
    const float* bq = (const float*)d_in[4];
    const float* Wk = (const float*)d_in[5];
    const float* bk = (const float*)d_in[6];
    const float* Wv = (const float*)d_in[7];
    const float* bv = (const float*)d_in[8];
    const float* Wo = (const float*)d_in[9];
    const float* bo = (const float*)d_in[10];
    const int* clip = (const int*)d_in[11];

    // Decide output layout from out_size: out-only / out+attn / attn-only
    float* outPtr  = (float*)d_out;       // nullptr -> kernel writes g_out scratch
    float* attnPtr = nullptr;             // nullptr -> kernel writes g_attn scratch
    const size_t osz = (size_t)out_size;
    if (osz >= OUT_ELEMS + ATTN_ELEMS) {
        attnPtr = (float*)d_out + OUT_ELEMS;
    } else if (osz == ATTN_ELEMS) {
        attnPtr = (float*)d_out;
        outPtr  = nullptr;
    }

    dim3 gproj(Dc/128, MROWS/128);   // (8, 32)

    // q = inputs@Wq + bq + relpos ; k = context@Wk + bk ; v = context@Wv + bv + relpos
    sgemm_bias<<<gproj, 256>>>(inputs,  Wq, bq, nullptr, 0, 0, 1, clip);
    sgemm_bias<<<gproj, 256>>>(context, Wk, bk, nullptr, 0, 1, 0, clip);
    sgemm_bias<<<gproj, 256>>>(context, Wv, bv, nullptr, 0, 2, 1, clip);

    const int attnSmem = (128*RPAD + 64*RPAD + 256) * 4;   // 53,248 B
    cudaFuncSetAttribute(attn_kernel, cudaFuncAttributeMaxDynamicSharedMemorySize, attnSmem);
    attn_kernel<<<dim3(Sc/128, Hc, Bc), 256, attnSmem>>>(mask, attnPtr);

    // out = av @ Wo + bo
    sgemm_bias<<<gproj, 256>>>(nullptr, Wo, bo, outPtr, 1, 3, 0, clip);
}